// round 7
// baseline (speedup 1.0000x reference)
#include <cuda_runtime.h>
#include <cuda_fp16.h>
#include <cstdint>
#include <cstddef>

#define DEVI __device__ __forceinline__

static constexpr int Bb = 256, Tt = 100, Dd = 4096, Hh = 1024;

// ---- device scratch (no allocs allowed) ----
__device__ __half g_KFinvT[(size_t)Hh * Dd];  // [H][D]
__device__ __half g_ZT[(size_t)Dd * Hh];      // [D][H]
__device__ __half g_diff[(size_t)Bb * Dd];    // [B][D]
__device__ __half g_hidden[(size_t)Bb * Hh];  // [B][H]

// ---- helpers ----
DEVI uint32_t smem_u32(const void* p) {
    uint32_t a;
    asm("{ .reg .u64 t; cvta.to.shared.u64 t, %1; cvt.u32.u64 %0, t; }" : "=r"(a) : "l"(p));
    return a;
}
DEVI uint32_t sw128(uint32_t off) { return off ^ ((off >> 3) & 0x70); }

DEVI void cp16(uint32_t dst, const void* src) {
    asm volatile("cp.async.cg.shared.global [%0], [%1], 16;" :: "r"(dst), "l"(src) : "memory");
}
DEVI void cp_commit() { asm volatile("cp.async.commit_group;" ::: "memory"); }
template <int N> DEVI void cp_wait() { asm volatile("cp.async.wait_group %0;" :: "n"(N) : "memory"); }

DEVI void ldsm_x4(uint32_t (&r)[4], uint32_t addr) {
    asm volatile("ldmatrix.sync.aligned.m8n8.x4.shared.b16 {%0, %1, %2, %3}, [%4];"
                 : "=r"(r[0]), "=r"(r[1]), "=r"(r[2]), "=r"(r[3]) : "r"(addr));
}
DEVI void mma16816(float (&d)[4], const uint32_t (&a)[4], const uint32_t* b) {
    asm volatile(
        "mma.sync.aligned.m16n8k16.row.col.f32.f16.f16.f32 "
        "{%0, %1, %2, %3}, {%4, %5, %6, %7}, {%8, %9}, {%0, %1, %2, %3};"
        : "+f"(d[0]), "+f"(d[1]), "+f"(d[2]), "+f"(d[3])
        : "r"(a[0]), "r"(a[1]), "r"(a[2]), "r"(a[3]), "r"(b[0]), "r"(b[1]));
}

// ---- GEMM step kernel (HMMA mma.sync path; tcgen05 blocked by compute_103 virtual arch) ----
// BK=128 stored as two contiguous [rows]x128B SW128 subtiles per operand tile.
// MODE 0: g_hidden = g_diff @ KFinvT^T + b_hidden          (M=256, N=1024, K=4096)
// MODE 1: nb = sigmoid(g_hidden @ ZT^T + b_out); out[:,t,:]=nb; g_diff = x[:,t+1,:]-nb
//                                                          (M=256, N=4096, K=1024)
template <int BM, int BN, int WMC, int WNC, int NT, int MODE>
__global__ __launch_bounds__(NT)
void gemm_step(int t, const float* __restrict__ bias,
               float* __restrict__ out, const float* __restrict__ xin) {
    constexpr int BK = 128;
    constexpr int WM = BM / WMC;       // 32
    constexpr int WN = BN / WNC;       // 16 or 32
    constexpr int MF = WM / 16;        // 2
    constexpr int NF = WN / 8;         // 2 or 4
    constexpr int K  = (MODE == 0) ? Dd : Hh;
    constexpr int KT = K / BK;         // 32 or 8
    constexpr int ABYTES = BM * 256;   // BK=128 halves = 256B per row (2 subtiles)
    constexpr int BBYTES = BN * 256;
    constexpr int STAGE  = ABYTES + BBYTES;

    extern __shared__ __align__(1024) char smem[];
    const uint32_t sb = smem_u32(smem);

    const int tid = threadIdx.x;
    const int wid = tid >> 5, lane = tid & 31;
    const int wm = wid % WMC, wn = wid / WMC;
    const int mt = blockIdx.y, nt = blockIdx.x;

    const __half* Ap;
    const __half* Bp;
    if (MODE == 0) { Ap = g_diff   + (size_t)mt * BM * Dd; Bp = g_KFinvT + (size_t)nt * BN * Dd; }
    else           { Ap = g_hidden + (size_t)mt * BM * Hh; Bp = g_ZT     + (size_t)nt * BN * Hh; }

    auto load_tile = [&](int kt, int stage) {
        const uint32_t sA = sb + stage * STAGE;
        const uint32_t sB = sA + ABYTES;
        const __half* ap = Ap + (size_t)kt * BK;
        const __half* bp = Bp + (size_t)kt * BK;
        #pragma unroll
        for (int c = tid; c < BM * 16; c += NT) {
            int row = c >> 4, col = c & 15;   // col in 16B units across 256B row
            uint32_t off = (uint32_t)(col >> 3) * (BM * 128) +
                           sw128((uint32_t)(row * 128 + (col & 7) * 16));
            cp16(sA + off, ap + (size_t)row * K + col * 8);
        }
        #pragma unroll
        for (int c = tid; c < BN * 16; c += NT) {
            int row = c >> 4, col = c & 15;
            uint32_t off = (uint32_t)(col >> 3) * (BN * 128) +
                           sw128((uint32_t)(row * 128 + (col & 7) * 16));
            cp16(sB + off, bp + (size_t)row * K + col * 8);
        }
        cp_commit();
    };

    load_tile(0, 0);
    load_tile(1, 1);

    float acc[MF][NF][4];
    #pragma unroll
    for (int mi = 0; mi < MF; mi++)
        #pragma unroll
        for (int ni = 0; ni < NF; ni++)
            #pragma unroll
            for (int q = 0; q < 4; q++) acc[mi][ni][q] = 0.0f;

    // lane-invariant parts of ldmatrix addresses
    const int a_row_l = ((lane >> 3) & 1) * 8 + (lane & 7);  // + mi*16 + wm*WM
    const int a_kc_l  = (lane >> 4) * 8;                     // + (ks&3)*16
    const int b_row_l = (lane >> 4) * 8 + (lane & 7);        // + bj*16 + wn*WN
    const int b_kc_l  = ((lane >> 3) & 1) * 8;               // + (ks&3)*16

    for (int i = 0; i < KT; i++) {
        if (i + 2 < KT) { cp_wait<1>(); } else { cp_wait<0>(); }
        __syncthreads();
        if (i + 2 < KT) load_tile(i + 2, (i + 2) % 3);

        const uint32_t sA = sb + (i % 3) * STAGE;
        const uint32_t sB = sA + ABYTES;

        #pragma unroll
        for (int ks = 0; ks < 8; ks++) {                     // 8 x k16 = BK 128
            const uint32_t sAk = sA + (uint32_t)(ks >> 2) * (BM * 128);
            const uint32_t sBk = sB + (uint32_t)(ks >> 2) * (BN * 128);
            const int kc = (ks & 3) * 16;
            uint32_t a[MF][4];
            #pragma unroll
            for (int mi = 0; mi < MF; mi++) {
                int row = wm * WM + mi * 16 + a_row_l;
                ldsm_x4(a[mi], sAk + sw128((uint32_t)(row * 128 + (kc + a_kc_l) * 2)));
            }
            uint32_t b[NF][2];
            #pragma unroll
            for (int bj = 0; bj < NF / 2; bj++) {
                int row = wn * WN + bj * 16 + b_row_l;
                uint32_t r[4];
                ldsm_x4(r, sBk + sw128((uint32_t)(row * 128 + (kc + b_kc_l) * 2)));
                b[2 * bj][0] = r[0]; b[2 * bj][1] = r[1];
                b[2 * bj + 1][0] = r[2]; b[2 * bj + 1][1] = r[3];
            }
            #pragma unroll
            for (int mi = 0; mi < MF; mi++)
                #pragma unroll
                for (int ni = 0; ni < NF; ni++)
                    mma16816(acc[mi][ni], a[mi], b[ni]);
        }
    }

    // ---- epilogue ----
    const int g  = lane >> 2;
    const int c2 = (lane & 3) * 2;
    const int m_base = mt * BM + wm * WM;
    const int n_base = nt * BN + wn * WN;

    #pragma unroll
    for (int mi = 0; mi < MF; mi++) {
        #pragma unroll
        for (int ni = 0; ni < NF; ni++) {
            const int col = n_base + ni * 8 + c2;
            const float b0 = __ldg(bias + col);
            const float b1 = __ldg(bias + col + 1);
            #pragma unroll
            for (int h = 0; h < 2; h++) {           // h=0 -> row g, h=1 -> row g+8
                const int row = m_base + mi * 16 + g + h * 8;
                const float v0 = acc[mi][ni][2 * h]     + b0;
                const float v1 = acc[mi][ni][2 * h + 1] + b1;
                if (MODE == 0) {
                    *reinterpret_cast<half2*>(g_hidden + (size_t)row * Hh + col) =
                        __floats2half2_rn(v0, v1);
                } else {
                    const float s0 = 1.0f / (1.0f + __expf(-v0));
                    const float s1 = 1.0f / (1.0f + __expf(-v1));
                    float2 s2; s2.x = s0; s2.y = s1;
                    __stcs(reinterpret_cast<float2*>(
                               out + ((size_t)row * Tt + t) * Dd + col), s2);
                    if (t + 1 < Tt) {
                        float2 xv = __ldcs(reinterpret_cast<const float2*>(
                                        xin + ((size_t)row * Tt + (t + 1)) * Dd + col));
                        *reinterpret_cast<half2*>(g_diff + (size_t)row * Dd + col) =
                            __floats2half2_rn(xv.x - s0, xv.y - s1);
                    }
                }
            }
        }
    }
}

// ---- prep kernels ----
// dst[c*R + r] = (half)src[r*C + c]; which==0 -> g_KFinvT, which==1 -> g_ZT
__global__ void transpose_to_half_kernel(const float* __restrict__ src, int which, int R, int C) {
    __shared__ float tile[32][33];
    __half* dst = which ? g_ZT : g_KFinvT;
    const int cb = blockIdx.x * 32, rb = blockIdx.y * 32;
    const int x = threadIdx.x, y = threadIdx.y;
    #pragma unroll
    for (int j = 0; j < 32; j += 8)
        tile[y + j][x] = src[(size_t)(rb + y + j) * C + (cb + x)];
    __syncthreads();
    #pragma unroll
    for (int j = 0; j < 32; j += 8)
        dst[(size_t)(cb + y + j) * R + (rb + x)] = __float2half(tile[x][y + j]);
}

// diff0 = x[:, 0, :] - b_out  (step-0 next_basket is b_out, no sigmoid)
__global__ void init_diff_kernel(const float* __restrict__ x, const float* __restrict__ b_out) {
    int i = blockIdx.x * blockDim.x + threadIdx.x;
    if (i >= Bb * Dd) return;
    int b = i / Dd, d = i - b * Dd;
    g_diff[i] = __float2half(x[(size_t)b * Tt * Dd + d] - b_out[d]);
}

// ---- launch ----
extern "C" void kernel_launch(void* const* d_in, const int* in_sizes, int n_in,
                              void* d_out, int out_size) {
    (void)in_sizes; (void)n_in; (void)out_size;
    const float* x        = (const float*)d_in[0];
    const float* Z        = (const float*)d_in[1];
    const float* b_out    = (const float*)d_in[2];
    const float* KFinv    = (const float*)d_in[3];
    const float* b_hidden = (const float*)d_in[4];
    float* out = (float*)d_out;

    // GEMM1: BM=64, BN=32 -> 128 CTAs; smem 3*(64+32)*256 = 73728
    // GEMM2: BM=128, BN=64 -> 128 CTAs; smem 3*(128+64)*256 = 147456
    constexpr int SMEM1 = 3 * (64 * 256 + 32 * 256);
    constexpr int SMEM2 = 3 * (128 * 256 + 64 * 256);
    auto k1 = gemm_step<64, 32, 2, 2, 128, 0>;
    auto k2 = gemm_step<128, 64, 4, 2, 256, 1>;
    cudaFuncSetAttribute(k1, cudaFuncAttributeMaxDynamicSharedMemorySize, SMEM1);
    cudaFuncSetAttribute(k2, cudaFuncAttributeMaxDynamicSharedMemorySize, SMEM2);

    transpose_to_half_kernel<<<dim3(Hh / 32, Dd / 32), dim3(32, 8)>>>(KFinv, 0, Dd, Hh);
    transpose_to_half_kernel<<<dim3(Dd / 32, Hh / 32), dim3(32, 8)>>>(Z, 1, Hh, Dd);
    init_diff_kernel<<<(Bb * Dd + 255) / 256, 256>>>(x, b_out);

    for (int t = 0; t < Tt; t++) {
        k1<<<dim3(Hh / 32, Bb / 64),  128, SMEM1>>>(t, b_hidden, out, x);
        k2<<<dim3(Dd / 64, Bb / 128), 256, SMEM2>>>(t, b_out, out, x);
    }
}

// round 8
// speedup vs baseline: 1.1205x; 1.1205x over previous
#include <cuda_runtime.h>
#include <cuda_fp16.h>
#include <cstdint>
#include <cstddef>

#define DEVI __device__ __forceinline__

static constexpr int Bb = 256, Tt = 100, Dd = 4096, Hh = 1024;

// ---- device scratch (no allocs allowed) ----
__device__ __half g_KFinvT[(size_t)Hh * Dd];  // [H][D]
__device__ __half g_ZT[(size_t)Dd * Hh];      // [D][H]
__device__ __half g_diff[(size_t)Bb * Dd];    // [B][D]
__device__ __half g_hidden[(size_t)Bb * Hh];  // [B][H]

// ---- helpers ----
DEVI uint32_t smem_u32(const void* p) {
    uint32_t a;
    asm("{ .reg .u64 t; cvta.to.shared.u64 t, %1; cvt.u32.u64 %0, t; }" : "=r"(a) : "l"(p));
    return a;
}
DEVI uint32_t sw128(uint32_t off) { return off ^ ((off >> 3) & 0x70); }

DEVI void cp16(uint32_t dst, const void* src) {
    asm volatile("cp.async.cg.shared.global [%0], [%1], 16;" :: "r"(dst), "l"(src) : "memory");
}
DEVI void cp_commit() { asm volatile("cp.async.commit_group;" ::: "memory"); }
template <int N> DEVI void cp_wait() { asm volatile("cp.async.wait_group %0;" :: "n"(N) : "memory"); }

DEVI void ldsm_x4(uint32_t (&r)[4], uint32_t addr) {
    asm volatile("ldmatrix.sync.aligned.m8n8.x4.shared.b16 {%0, %1, %2, %3}, [%4];"
                 : "=r"(r[0]), "=r"(r[1]), "=r"(r[2]), "=r"(r[3]) : "r"(addr));
}
DEVI void mma16816(float (&d)[4], const uint32_t (&a)[4], const uint32_t* b) {
    asm volatile(
        "mma.sync.aligned.m16n8k16.row.col.f32.f16.f16.f32 "
        "{%0, %1, %2, %3}, {%4, %5, %6, %7}, {%8, %9}, {%0, %1, %2, %3};"
        : "+f"(d[0]), "+f"(d[1]), "+f"(d[2]), "+f"(d[3])
        : "r"(a[0]), "r"(a[1]), "r"(a[2]), "r"(a[3]), "r"(b[0]), "r"(b[1]));
}

// ---- GEMM step kernel (HMMA mma.sync; intra-CTA split-K=2 across warp halves) ----
// BK=128 stored as two contiguous [rows]x128B SW128 subtiles; kk-half reads subtile kk.
// MODE 0: g_hidden = g_diff @ KFinvT^T + b_hidden          (M=256, N=1024, K=4096)
// MODE 1: nb = sigmoid(g_hidden @ ZT^T + b_out); out[:,t,:]=nb; g_diff = x[:,t+1,:]-nb
//                                                          (M=256, N=4096, K=1024)
template <int BM, int BN, int WMC, int WNC, int NT, int MODE>
__global__ __launch_bounds__(NT, 1)
void gemm_step(int t, const float* __restrict__ bias,
               float* __restrict__ out, const float* __restrict__ xin) {
    constexpr int BK = 128;
    constexpr int WM = BM / WMC;       // 32
    constexpr int WN = BN / WNC;       // 16 or 32
    constexpr int MF = WM / 16;        // 2
    constexpr int NF = WN / 8;         // 2 or 4
    constexpr int HALF = WMC * WNC;    // warps per K-half
    constexpr int K  = (MODE == 0) ? Dd : Hh;
    constexpr int KT = K / BK;         // 32 or 8
    constexpr int ABYTES = BM * 256;   // BK=128 halves = 256B per row (2 subtiles)
    constexpr int BBYTES = BN * 256;
    constexpr int STAGE  = ABYTES + BBYTES;

    extern __shared__ __align__(1024) char smem[];
    const uint32_t sb = smem_u32(smem);

    const int tid = threadIdx.x;
    const int wid = tid >> 5, lane = tid & 31;
    const int kk = (wid >= HALF) ? 1 : 0;
    const int inner = wid - kk * HALF;
    const int wm = inner % WMC, wn = inner / WMC;
    const int mt = blockIdx.y, nt = blockIdx.x;

    const __half* Ap;
    const __half* Bp;
    if (MODE == 0) { Ap = g_diff   + (size_t)mt * BM * Dd; Bp = g_KFinvT + (size_t)nt * BN * Dd; }
    else           { Ap = g_hidden + (size_t)mt * BM * Hh; Bp = g_ZT     + (size_t)nt * BN * Hh; }

    auto load_tile = [&](int kt, int stage) {
        const uint32_t sA = sb + stage * STAGE;
        const uint32_t sB = sA + ABYTES;
        const __half* ap = Ap + (size_t)kt * BK;
        const __half* bp = Bp + (size_t)kt * BK;
        #pragma unroll
        for (int c = tid; c < BM * 16; c += NT) {
            int row = c >> 4, col = c & 15;   // col in 16B units across 256B row
            uint32_t off = (uint32_t)(col >> 3) * (BM * 128) +
                           sw128((uint32_t)(row * 128 + (col & 7) * 16));
            cp16(sA + off, ap + (size_t)row * K + col * 8);
        }
        #pragma unroll
        for (int c = tid; c < BN * 16; c += NT) {
            int row = c >> 4, col = c & 15;
            uint32_t off = (uint32_t)(col >> 3) * (BN * 128) +
                           sw128((uint32_t)(row * 128 + (col & 7) * 16));
            cp16(sB + off, bp + (size_t)row * K + col * 8);
        }
        cp_commit();
    };

    load_tile(0, 0);
    load_tile(1, 1);

    float acc[MF][NF][4];
    #pragma unroll
    for (int mi = 0; mi < MF; mi++)
        #pragma unroll
        for (int ni = 0; ni < NF; ni++)
            #pragma unroll
            for (int q = 0; q < 4; q++) acc[mi][ni][q] = 0.0f;

    // lane-invariant parts of ldmatrix addresses
    const int a_row_l = ((lane >> 3) & 1) * 8 + (lane & 7);  // + mi*16 + wm*WM
    const int a_kc_l  = (lane >> 4) * 8;                     // + ks4*16
    const int b_row_l = (lane >> 4) * 8 + (lane & 7);        // + bj*16 + wn*WN
    const int b_kc_l  = ((lane >> 3) & 1) * 8;               // + ks4*16
    const uint32_t a_sub = (uint32_t)kk * (BM * 128);        // this half's subtile
    const uint32_t b_sub = (uint32_t)kk * (BN * 128);

    for (int i = 0; i < KT; i++) {
        if (i + 2 < KT) { cp_wait<1>(); } else { cp_wait<0>(); }
        __syncthreads();
        if (i + 2 < KT) load_tile(i + 2, (i + 2) % 3);

        const uint32_t sAk = sb + (i % 3) * STAGE + a_sub;
        const uint32_t sBk = sb + (i % 3) * STAGE + ABYTES + b_sub;

        #pragma unroll
        for (int ks4 = 0; ks4 < 4; ks4++) {                  // 4 x k16 per half
            const int kc = ks4 * 16;
            uint32_t a[MF][4];
            #pragma unroll
            for (int mi = 0; mi < MF; mi++) {
                int row = wm * WM + mi * 16 + a_row_l;
                ldsm_x4(a[mi], sAk + sw128((uint32_t)(row * 128 + (kc + a_kc_l) * 2)));
            }
            uint32_t b[NF][2];
            #pragma unroll
            for (int bj = 0; bj < NF / 2; bj++) {
                int row = wn * WN + bj * 16 + b_row_l;
                uint32_t r[4];
                ldsm_x4(r, sBk + sw128((uint32_t)(row * 128 + (kc + b_kc_l) * 2)));
                b[2 * bj][0] = r[0]; b[2 * bj][1] = r[1];
                b[2 * bj + 1][0] = r[2]; b[2 * bj + 1][1] = r[3];
            }
            #pragma unroll
            for (int mi = 0; mi < MF; mi++)
                #pragma unroll
                for (int ni = 0; ni < NF; ni++)
                    mma16816(acc[mi][ni], a[mi], b[ni]);
        }
    }

    // ---- split-K reduction: kk=1 warps dump to (now free) smem, kk=0 adds ----
    __syncthreads();   // all MMAs done; tile smem reusable
    float4* red = reinterpret_cast<float4*>(smem);
    const int rslot = (inner * 32 + lane) * (MF * NF);
    if (kk == 1) {
        #pragma unroll
        for (int mi = 0; mi < MF; mi++)
            #pragma unroll
            for (int ni = 0; ni < NF; ni++) {
                float4 v;
                v.x = acc[mi][ni][0]; v.y = acc[mi][ni][1];
                v.z = acc[mi][ni][2]; v.w = acc[mi][ni][3];
                red[rslot + mi * NF + ni] = v;
            }
    }
    __syncthreads();
    if (kk == 1) return;

    #pragma unroll
    for (int mi = 0; mi < MF; mi++)
        #pragma unroll
        for (int ni = 0; ni < NF; ni++) {
            float4 v = red[rslot + mi * NF + ni];
            acc[mi][ni][0] += v.x; acc[mi][ni][1] += v.y;
            acc[mi][ni][2] += v.z; acc[mi][ni][3] += v.w;
        }

    // ---- epilogue (kk=0 warps only) ----
    const int g  = lane >> 2;
    const int c2 = (lane & 3) * 2;
    const int m_base = mt * BM + wm * WM;
    const int n_base = nt * BN + wn * WN;

    #pragma unroll
    for (int mi = 0; mi < MF; mi++) {
        #pragma unroll
        for (int ni = 0; ni < NF; ni++) {
            const int col = n_base + ni * 8 + c2;
            const float b0 = __ldg(bias + col);
            const float b1 = __ldg(bias + col + 1);
            #pragma unroll
            for (int h = 0; h < 2; h++) {           // h=0 -> row g, h=1 -> row g+8
                const int row = m_base + mi * 16 + g + h * 8;
                const float v0 = acc[mi][ni][2 * h]     + b0;
                const float v1 = acc[mi][ni][2 * h + 1] + b1;
                if (MODE == 0) {
                    *reinterpret_cast<half2*>(g_hidden + (size_t)row * Hh + col) =
                        __floats2half2_rn(v0, v1);
                } else {
                    const float s0 = 1.0f / (1.0f + __expf(-v0));
                    const float s1 = 1.0f / (1.0f + __expf(-v1));
                    float2 s2; s2.x = s0; s2.y = s1;
                    __stcs(reinterpret_cast<float2*>(
                               out + ((size_t)row * Tt + t) * Dd + col), s2);
                    if (t + 1 < Tt) {
                        float2 xv = __ldcs(reinterpret_cast<const float2*>(
                                        xin + ((size_t)row * Tt + (t + 1)) * Dd + col));
                        *reinterpret_cast<half2*>(g_diff + (size_t)row * Dd + col) =
                            __floats2half2_rn(xv.x - s0, xv.y - s1);
                    }
                }
            }
        }
    }
}

// ---- prep kernels ----
// dst[c*R + r] = (half)src[r*C + c]; which==0 -> g_KFinvT, which==1 -> g_ZT
__global__ void transpose_to_half_kernel(const float* __restrict__ src, int which, int R, int C) {
    __shared__ float tile[32][33];
    __half* dst = which ? g_ZT : g_KFinvT;
    const int cb = blockIdx.x * 32, rb = blockIdx.y * 32;
    const int x = threadIdx.x, y = threadIdx.y;
    #pragma unroll
    for (int j = 0; j < 32; j += 8)
        tile[y + j][x] = src[(size_t)(rb + y + j) * C + (cb + x)];
    __syncthreads();
    #pragma unroll
    for (int j = 0; j < 32; j += 8)
        dst[(size_t)(cb + y + j) * R + (rb + x)] = __float2half(tile[x][y + j]);
}

// diff0 = x[:, 0, :] - b_out  (step-0 next_basket is b_out, no sigmoid)
__global__ void init_diff_kernel(const float* __restrict__ x, const float* __restrict__ b_out) {
    int i = blockIdx.x * blockDim.x + threadIdx.x;
    if (i >= Bb * Dd) return;
    int b = i / Dd, d = i - b * Dd;
    g_diff[i] = __float2half(x[(size_t)b * Tt * Dd + d] - b_out[d]);
}

// ---- launch ----
extern "C" void kernel_launch(void* const* d_in, const int* in_sizes, int n_in,
                              void* d_out, int out_size) {
    (void)in_sizes; (void)n_in; (void)out_size;
    const float* x        = (const float*)d_in[0];
    const float* Z        = (const float*)d_in[1];
    const float* b_out    = (const float*)d_in[2];
    const float* KFinv    = (const float*)d_in[3];
    const float* b_hidden = (const float*)d_in[4];
    float* out = (float*)d_out;

    // GEMM1: BM=64, BN=32, 256 thr (8 warps, split-K=2) -> 128 CTAs; smem 73728
    // GEMM2: BM=128, BN=64, 512 thr (16 warps, split-K=2) -> 128 CTAs; smem 147456
    constexpr int SMEM1 = 3 * (64 * 256 + 32 * 256);
    constexpr int SMEM2 = 3 * (128 * 256 + 64 * 256);
    auto k1 = gemm_step<64, 32, 2, 2, 256, 0>;
    auto k2 = gemm_step<128, 64, 4, 2, 512, 1>;
    cudaFuncSetAttribute(k1, cudaFuncAttributeMaxDynamicSharedMemorySize, SMEM1);
    cudaFuncSetAttribute(k2, cudaFuncAttributeMaxDynamicSharedMemorySize, SMEM2);

    transpose_to_half_kernel<<<dim3(Hh / 32, Dd / 32), dim3(32, 8)>>>(KFinv, 0, Dd, Hh);
    transpose_to_half_kernel<<<dim3(Dd / 32, Hh / 32), dim3(32, 8)>>>(Z, 1, Hh, Dd);
    init_diff_kernel<<<(Bb * Dd + 255) / 256, 256>>>(x, b_out);

    for (int t = 0; t < Tt; t++) {
        k1<<<dim3(Hh / 32, Bb / 64),  256, SMEM1>>>(t, b_hidden, out, x);
        k2<<<dim3(Dd / 64, Bb / 128), 512, SMEM2>>>(t, b_out, out, x);
    }
}

// round 16
// speedup vs baseline: 1.1773x; 1.0507x over previous
#include <cuda_runtime.h>
#include <cuda_fp16.h>
#include <cstdint>
#include <cstddef>

#define DEVI __device__ __forceinline__

static constexpr int Bb = 256, Tt = 100, Dd = 4096, Hh = 1024;

// ---- device scratch (no allocs allowed) ----
__device__ __half g_KFinvT[(size_t)Hh * Dd];  // [H][D]
__device__ __half g_ZT[(size_t)Dd * Hh];      // [D][H]
__device__ __half g_diff[(size_t)Bb * Dd];    // [B][D]
__device__ __half g_hidden[(size_t)Bb * Hh];  // [B][H]

// ---- helpers ----
DEVI uint32_t smem_u32(const void* p) {
    uint32_t a;
    asm("{ .reg .u64 t; cvta.to.shared.u64 t, %1; cvt.u32.u64 %0, t; }" : "=r"(a) : "l"(p));
    return a;
}
DEVI uint32_t sw128(uint32_t off) { return off ^ ((off >> 3) & 0x70); }

DEVI void cp16(uint32_t dst, const void* src) {
    asm volatile("cp.async.cg.shared.global [%0], [%1], 16;" :: "r"(dst), "l"(src) : "memory");
}
DEVI void cp_commit() { asm volatile("cp.async.commit_group;" ::: "memory"); }
template <int N> DEVI void cp_wait() { asm volatile("cp.async.wait_group %0;" :: "n"(N) : "memory"); }

DEVI void ldsm_x4(uint32_t (&r)[4], uint32_t addr) {
    asm volatile("ldmatrix.sync.aligned.m8n8.x4.shared.b16 {%0, %1, %2, %3}, [%4];"
                 : "=r"(r[0]), "=r"(r[1]), "=r"(r[2]), "=r"(r[3]) : "r"(addr));
}
DEVI void mma16816(float (&d)[4], const uint32_t (&a)[4], const uint32_t* b) {
    asm volatile(
        "mma.sync.aligned.m16n8k16.row.col.f32.f16.f16.f32 "
        "{%0, %1, %2, %3}, {%4, %5, %6, %7}, {%8, %9}, {%0, %1, %2, %3};"
        : "+f"(d[0]), "+f"(d[1]), "+f"(d[2]), "+f"(d[3])
        : "r"(a[0]), "r"(a[1]), "r"(a[2]), "r"(a[3]), "r"(b[0]), "r"(b[1]));
}

// ---- GEMM step kernel (HMMA mma.sync; intra-CTA split-K across warp groups) ----
// BK=128 stored as two contiguous [rows]x128B SW128 subtiles.
// Warp group kk handles k16 steps ksg = kk*(8/KSPLIT) .. +(8/KSPLIT)-1;
// subtile = ksg>>2, column = (ksg&3)*16.
// MODE 0: g_hidden = g_diff @ KFinvT^T + b_hidden          (M=256, N=1024, K=4096)
// MODE 1: nb = sigmoid(g_hidden @ ZT^T + b_out); out[:,t,:]=nb; g_diff = x[:,t+1,:]-nb
//                                                          (M=256, N=4096, K=1024)
template <int BM, int BN, int WMC, int WNC, int KSPLIT, int MODE>
__global__ __launch_bounds__(32 * WMC * WNC * KSPLIT, 1)
void gemm_step(int t, const float* __restrict__ bias,
               float* __restrict__ out, const float* __restrict__ xin) {
    constexpr int NT = 32 * WMC * WNC * KSPLIT;
    constexpr int WM = BM / WMC;       // 32
    constexpr int WN = BN / WNC;       // 16 or 32
    constexpr int MF = WM / 16;        // 2
    constexpr int NF = WN / 8;         // 2 or 4
    constexpr int INNER = WMC * WNC;   // warps per K-group
    constexpr int SPK = 8 / KSPLIT;    // k16 steps per K-group per tile
    constexpr int BK = 128;
    constexpr int K  = (MODE == 0) ? Dd : Hh;
    constexpr int KT = K / BK;         // 32 or 8
    constexpr int ABYTES = BM * 256;   // BK=128 halves = 256B per row (2 subtiles)
    constexpr int BBYTES = BN * 256;
    constexpr int STAGE  = ABYTES + BBYTES;

    extern __shared__ __align__(1024) char smem[];
    const uint32_t sb = smem_u32(smem);

    const int tid = threadIdx.x;
    const int wid = tid >> 5, lane = tid & 31;
    const int kk = wid / INNER;
    const int inner = wid % INNER;
    const int wm = inner % WMC, wn = inner / WMC;
    const int mt = blockIdx.y, nt = blockIdx.x;

    const __half* Ap;
    const __half* Bp;
    if (MODE == 0) { Ap = g_diff   + (size_t)mt * BM * Dd; Bp = g_KFinvT + (size_t)nt * BN * Dd; }
    else           { Ap = g_hidden + (size_t)mt * BM * Hh; Bp = g_ZT     + (size_t)nt * BN * Hh; }

    auto load_tile = [&](int kt, int stage) {
        const uint32_t sA = sb + stage * STAGE;
        const uint32_t sB = sA + ABYTES;
        const __half* ap = Ap + (size_t)kt * BK;
        const __half* bp = Bp + (size_t)kt * BK;
        #pragma unroll
        for (int c = tid; c < BM * 16; c += NT) {
            int row = c >> 4, col = c & 15;   // col in 16B units across 256B row
            uint32_t off = (uint32_t)(col >> 3) * (BM * 128) +
                           sw128((uint32_t)(row * 128 + (col & 7) * 16));
            cp16(sA + off, ap + (size_t)row * K + col * 8);
        }
        #pragma unroll
        for (int c = tid; c < BN * 16; c += NT) {
            int row = c >> 4, col = c & 15;
            uint32_t off = (uint32_t)(col >> 3) * (BN * 128) +
                           sw128((uint32_t)(row * 128 + (col & 7) * 16));
            cp16(sB + off, bp + (size_t)row * K + col * 8);
        }
        cp_commit();
    };

    load_tile(0, 0);
    load_tile(1, 1);

    float acc[MF][NF][4];
    #pragma unroll
    for (int mi = 0; mi < MF; mi++)
        #pragma unroll
        for (int ni = 0; ni < NF; ni++)
            #pragma unroll
            for (int q = 0; q < 4; q++) acc[mi][ni][q] = 0.0f;

    // lane-invariant parts of ldmatrix addresses
    const int a_row_l = ((lane >> 3) & 1) * 8 + (lane & 7);  // + mi*16 + wm*WM
    const int a_kc_l  = (lane >> 4) * 8;                     // + kc
    const int b_row_l = (lane >> 4) * 8 + (lane & 7);        // + bj*16 + wn*WN
    const int b_kc_l  = ((lane >> 3) & 1) * 8;               // + kc

    for (int i = 0; i < KT; i++) {
        if (i + 2 < KT) { cp_wait<1>(); } else { cp_wait<0>(); }
        __syncthreads();
        if (i + 2 < KT) load_tile(i + 2, (i + 2) % 3);

        const uint32_t sA = sb + (i % 3) * STAGE;
        const uint32_t sB = sA + ABYTES;

        #pragma unroll
        for (int ks = 0; ks < SPK; ks++) {
            const int ksg = kk * SPK + ks;            // global k16 index 0..7
            const uint32_t sAk = sA + (uint32_t)(ksg >> 2) * (BM * 128);
            const uint32_t sBk = sB + (uint32_t)(ksg >> 2) * (BN * 128);
            const int kc = (ksg & 3) * 16;
            uint32_t a[MF][4];
            #pragma unroll
            for (int mi = 0; mi < MF; mi++) {
                int row = wm * WM + mi * 16 + a_row_l;
                ldsm_x4(a[mi], sAk + sw128((uint32_t)(row * 128 + (kc + a_kc_l) * 2)));
            }
            uint32_t b[NF][2];
            #pragma unroll
            for (int bj = 0; bj < NF / 2; bj++) {
                int row = wn * WN + bj * 16 + b_row_l;
                uint32_t r[4];
                ldsm_x4(r, sBk + sw128((uint32_t)(row * 128 + (kc + b_kc_l) * 2)));
                b[2 * bj][0] = r[0]; b[2 * bj][1] = r[1];
                b[2 * bj + 1][0] = r[2]; b[2 * bj + 1][1] = r[3];
            }
            #pragma unroll
            for (int mi = 0; mi < MF; mi++)
                #pragma unroll
                for (int ni = 0; ni < NF; ni++)
                    mma16816(acc[mi][ni], a[mi], b[ni]);
        }
    }

    // ---- split-K reduction: kk>0 warps dump to (now free) smem, kk=0 adds ----
    __syncthreads();   // all MMAs done; tile smem reusable
    float4* red = reinterpret_cast<float4*>(smem);
    if (kk > 0) {
        const int rslot = (((kk - 1) * INNER + inner) * 32 + lane) * (MF * NF);
        #pragma unroll
        for (int mi = 0; mi < MF; mi++)
            #pragma unroll
            for (int ni = 0; ni < NF; ni++) {
                float4 v;
                v.x = acc[mi][ni][0]; v.y = acc[mi][ni][1];
                v.z = acc[mi][ni][2]; v.w = acc[mi][ni][3];
                red[rslot + mi * NF + ni] = v;
            }
    }
    __syncthreads();
    if (kk > 0) return;

    #pragma unroll
    for (int kr = 0; kr < KSPLIT - 1; kr++) {
        const int rslot = ((kr * INNER + inner) * 32 + lane) * (MF * NF);
        #pragma unroll
        for (int mi = 0; mi < MF; mi++)
            #pragma unroll
            for (int ni = 0; ni < NF; ni++) {
                float4 v = red[rslot + mi * NF + ni];
                acc[mi][ni][0] += v.x; acc[mi][ni][1] += v.y;
                acc[mi][ni][2] += v.z; acc[mi][ni][3] += v.w;
            }
    }

    // ---- epilogue (kk=0 warps only) ----
    const int g  = lane >> 2;
    const int c2 = (lane & 3) * 2;
    const int m_base = mt * BM + wm * WM;
    const int n_base = nt * BN + wn * WN;

    #pragma unroll
    for (int mi = 0; mi < MF; mi++) {
        #pragma unroll
        for (int ni = 0; ni < NF; ni++) {
            const int col = n_base + ni * 8 + c2;
            const float b0 = __ldg(bias + col);
            const float b1 = __ldg(bias + col + 1);
            #pragma unroll
            for (int h = 0; h < 2; h++) {           // h=0 -> row g, h=1 -> row g+8
                const int row = m_base + mi * 16 + g + h * 8;
                const float v0 = acc[mi][ni][2 * h]     + b0;
                const float v1 = acc[mi][ni][2 * h + 1] + b1;
                if (MODE == 0) {
                    *reinterpret_cast<half2*>(g_hidden + (size_t)row * Hh + col) =
                        __floats2half2_rn(v0, v1);
                } else {
                    const float s0 = 1.0f / (1.0f + __expf(-v0));
                    const float s1 = 1.0f / (1.0f + __expf(-v1));
                    float2 s2; s2.x = s0; s2.y = s1;
                    __stcs(reinterpret_cast<float2*>(
                               out + ((size_t)row * Tt + t) * Dd + col), s2);
                    if (t + 1 < Tt) {
                        float2 xv = __ldcs(reinterpret_cast<const float2*>(
                                        xin + ((size_t)row * Tt + (t + 1)) * Dd + col));
                        *reinterpret_cast<half2*>(g_diff + (size_t)row * Dd + col) =
                            __floats2half2_rn(xv.x - s0, xv.y - s1);
                    }
                }
            }
        }
    }
}

// ---- prep kernels ----
// dst[c*R + r] = (half)src[r*C + c]; which==0 -> g_KFinvT, which==1 -> g_ZT
__global__ void transpose_to_half_kernel(const float* __restrict__ src, int which, int R, int C) {
    __shared__ float tile[32][33];
    __half* dst = which ? g_ZT : g_KFinvT;
    const int cb = blockIdx.x * 32, rb = blockIdx.y * 32;
    const int x = threadIdx.x, y = threadIdx.y;
    #pragma unroll
    for (int j = 0; j < 32; j += 8)
        tile[y + j][x] = src[(size_t)(rb + y + j) * C + (cb + x)];
    __syncthreads();
    #pragma unroll
    for (int j = 0; j < 32; j += 8)
        dst[(size_t)(cb + y + j) * R + (rb + x)] = __float2half(tile[x][y + j]);
}

// diff0 = x[:, 0, :] - b_out  (step-0 next_basket is b_out, no sigmoid)
__global__ void init_diff_kernel(const float* __restrict__ x, const float* __restrict__ b_out) {
    int i = blockIdx.x * blockDim.x + threadIdx.x;
    if (i >= Bb * Dd) return;
    int b = i / Dd, d = i - b * Dd;
    g_diff[i] = __float2half(x[(size_t)b * Tt * Dd + d] - b_out[d]);
}

// ---- launch ----
extern "C" void kernel_launch(void* const* d_in, const int* in_sizes, int n_in,
                              void* d_out, int out_size) {
    (void)in_sizes; (void)n_in; (void)out_size;
    const float* x        = (const float*)d_in[0];
    const float* Z        = (const float*)d_in[1];
    const float* b_out    = (const float*)d_in[2];
    const float* KFinv    = (const float*)d_in[3];
    const float* b_hidden = (const float*)d_in[4];
    float* out = (float*)d_out;

    // GEMM1: BM=64, BN=32, WMC=2, WNC=1 (MF=2,NF=4), split-K=8 -> 512 thr, 128 CTAs
    // GEMM2: BM=128, BN=64, WMC=4, WNC=2 (MF=2,NF=4), split-K=2 -> 512 thr, 128 CTAs
    constexpr int SMEM1 = 3 * (64 * 256 + 32 * 256);
    constexpr int SMEM2 = 3 * (128 * 256 + 64 * 256);
    auto k1 = gemm_step<64, 32, 2, 1, 8, 0>;
    auto k2 = gemm_step<128, 64, 4, 2, 2, 1>;
    cudaFuncSetAttribute(k1, cudaFuncAttributeMaxDynamicSharedMemorySize, SMEM1);
    cudaFuncSetAttribute(k2, cudaFuncAttributeMaxDynamicSharedMemorySize, SMEM2);

    transpose_to_half_kernel<<<dim3(Hh / 32, Dd / 32), dim3(32, 8)>>>(KFinv, 0, Dd, Hh);
    transpose_to_half_kernel<<<dim3(Dd / 32, Hh / 32), dim3(32, 8)>>>(Z, 1, Hh, Dd);
    init_diff_kernel<<<(Bb * Dd + 255) / 256, 256>>>(x, b_out);

    for (int t = 0; t < Tt; t++) {
        k1<<<dim3(Hh / 32, Bb / 64),  512, SMEM1>>>(t, b_hidden, out, x);
        k2<<<dim3(Dd / 64, Bb / 128), 512, SMEM2>>>(t, b_out, out, x);
    }
}